// round 5
// baseline (speedup 1.0000x reference)
#include <cuda_runtime.h>
#include <cstdint>

// CostVolumeLayer3D, B=2 C=64 D=32 H=64 W=64, R=2.
// out[b, ch(s,dsh), d, h, w] = (1/125) * sum_c x1[b,c,d,h,w] * x2[b,c,d-dsh,h-i_s,w-j_s]
//   s in [-4,4], dsh in [-2,2], (i_s,j_s) = (min(2,s+2), max(-2,s-2)),
//   ch = (5s+dsh) mod 125. Channels 23..102 are identically zero.
// Thread = (w-pair) x (d-pair): 4 voxels, 90 f32x2 accumulators.
// NO shared memory, NO barriers: direct predicated LDG.64 with immediate offsets;
// overlap across threads/warps served by L1. Register double-buffer over planes.

typedef unsigned long long ull;
#define LD64(p) (*reinterpret_cast<const ull*>(p))

static __device__ __forceinline__ ull pk2(uint32_t lo, uint32_t hi) {
    ull r; asm("mov.b64 %0, {%1,%2};" : "=l"(r) : "r"(lo), "r"(hi)); return r;
}
static __device__ __forceinline__ void unpk(uint32_t& lo, uint32_t& hi, ull v) {
    asm("mov.b64 {%0,%1}, %2;" : "=r"(lo), "=r"(hi) : "l"(v));
}
static __device__ __forceinline__ void fma2(ull& acc, ull a, ull b) {
    asm("fma.rn.f32x2 %0, %1, %2, %0;" : "+l"(acc) : "l"(a), "l"(b));
}
static __device__ __forceinline__ ull mul2(ull a, ull b) {
    ull r; asm("mul.rn.f32x2 %0, %1, %2;" : "=l"(r) : "l"(a), "l"(b)); return r;
}

// Load the 7 b-values of one x2 plane (plane float-offset po) into d[7].
// Offsets relative to bp = &x2[c][d0-2][gh-2][w]:
//   f0=-2, f2=0, f4=+2 (row gh-2); l1=+66, l2=+130, l3=+194, l4=+258 (col w+2, rows gh-1..gh+2)
static __device__ __forceinline__ void load_plane(
    ull d[7], const float* bp, int po,
    bool f0ok, bool f2ok, bool f4ok,
    bool l1ok, bool l2ok, bool l3ok, bool l4ok)
{
    d[0]=0; d[1]=0; d[2]=0; d[3]=0; d[4]=0; d[5]=0; d[6]=0;
    if (f0ok) d[0] = LD64(bp + po - 2);
    if (f2ok) d[1] = LD64(bp + po);
    if (f4ok) d[2] = LD64(bp + po + 2);
    if (l1ok) d[3] = LD64(bp + po + 66);
    if (l2ok) d[4] = LD64(bp + po + 130);
    if (l3ok) d[5] = LD64(bp + po + 194);
    if (l4ok) d[6] = LD64(bp + po + 258);
}

static __device__ __forceinline__ void compute_plane(
    const ull t[7], int p, ull A0, ull A1, ull acc[2][5][9])
{
    uint32_t f0lo, f0hi, f2lo, f2hi, f4lo, f4hi;
    unpk(f0lo, f0hi, t[0]); unpk(f2lo, f2hi, t[1]); unpk(f4lo, f4hi, t[2]);
    ull bb[9];
    bb[0] = t[6];               // s=-4: (gh+2, ww+2)
    bb[1] = t[5];               // s=-3
    bb[2] = t[4];               // s=-2
    bb[3] = t[3];               // s=-1
    bb[4] = t[2];               // s= 0: (gh-2, ww+2)
    bb[5] = pk2(f2hi, f4lo);    // s= 1
    bb[6] = t[1];               // s= 2
    bb[7] = pk2(f0hi, f2lo);    // s= 3
    bb[8] = t[0];               // s= 4
    if (p <= 4) {               // voxel d0:   u = 4-p
        #pragma unroll
        for (int v = 0; v < 9; ++v) fma2(acc[0][4 - p][v], A0, bb[v]);
    }
    if (p >= 1) {               // voxel d0+1: u = 5-p
        #pragma unroll
        for (int v = 0; v < 9; ++v) fma2(acc[1][5 - p][v], A1, bb[v]);
    }
}

// EDGE=true: full row/plane predication. EDGE=false: only per-lane W predicates.
template<bool EDGE>
static __device__ __forceinline__ void worker(
    ull acc[2][5][9], const float* bp, const float* x1p,
    bool wlo, bool whi,                    // (w>0), (w<62)
    bool r_f, bool r_l1, bool r_l3, bool r_l4,   // gh>=2, gh>=1, gh<=62, gh<=61
    const bool pd[6])
{
    // per-plane condition macro
#define CND(P) \
    (EDGE ? (r_f  && wlo && pd[P]) : wlo), \
    (EDGE ? (r_f  &&        pd[P]) : true), \
    (EDGE ? (r_f  && whi && pd[P]) : whi), \
    (EDGE ? (r_l1 && whi && pd[P]) : whi), \
    (EDGE ? (         whi && pd[P]) : whi), \
    (EDGE ? (r_l3 && whi && pd[P]) : whi), \
    (EDGE ? (r_l4 && whi && pd[P]) : whi)

    ull a[7], b[7];
    load_plane(a, bp, 0, CND(0));
    ull A0 = LD64(x1p), A1 = LD64(x1p + 4096);

    #pragma unroll 1
    for (int c = 0; c < 64; ++c) {
        ull A0n = A0, A1n = A1;
        if (c < 63) { A0n = LD64(x1p + 131072); A1n = LD64(x1p + 131072 + 4096); }
        x1p += 131072;

        load_plane(b, bp, 1 * 4096, CND(1));
        compute_plane(a, 0, A0, A1, acc);
        load_plane(a, bp, 2 * 4096, CND(2));
        compute_plane(b, 1, A0, A1, acc);
        load_plane(b, bp, 3 * 4096, CND(3));
        compute_plane(a, 2, A0, A1, acc);
        load_plane(a, bp, 4 * 4096, CND(4));
        compute_plane(b, 3, A0, A1, acc);
        load_plane(b, bp, 5 * 4096, CND(5));
        compute_plane(a, 4, A0, A1, acc);
        bp += 131072;
        if (c < 63) load_plane(a, bp, 0, CND(0));
        compute_plane(b, 5, A0, A1, acc);

        A0 = A0n; A1 = A1n;
    }
#undef CND
}

__global__ void __launch_bounds__(256, 1)
cv3d_kernel(const float* __restrict__ x1, const float* __restrict__ x2,
            float* __restrict__ out)
{
    const int tid = threadIdx.x;
    const int hl  = tid >> 5;           // 0..7: h row (warp = one row)
    const int w   = (tid & 31) * 2;     // even w; thread owns (w, w+1)
    const int h0  = blockIdx.x * 8;
    const int d0  = blockIdx.y * 2;
    const int b   = blockIdx.z;
    const int gh  = h0 + hl;

    const float* x1b = x1 + (size_t)b * 8388608;
    const float* x2b = x2 + (size_t)b * 8388608;

    // ---- zero the 80 never-written output channels (23..102) for this tile ----
    {
        float* zb = out + (size_t)b * 16384000 + (size_t)23 * 131072
                        + (size_t)d0 * 4096 + (size_t)h0 * 64;
        int dd = tid >> 7, row = (tid >> 4) & 7, cw = tid & 15;
        float* base = zb + dd * 4096 + row * 64 + cw * 4;
        const float4 z = make_float4(0.f, 0.f, 0.f, 0.f);
        #pragma unroll 4
        for (int ch = 0; ch < 80; ++ch)
            *reinterpret_cast<float4*>(base + (size_t)ch * 131072) = z;
    }

    // ---- accumulators: [d-index][dsh+2][s+4], f32x2 lanes = (w, w+1) ----
    ull acc[2][5][9];
    #pragma unroll
    for (int a = 0; a < 2; ++a)
        #pragma unroll
        for (int u = 0; u < 5; ++u)
            #pragma unroll
            for (int v = 0; v < 9; ++v) acc[a][u][v] = 0ull;

    // base pointer: &x2[b][0][d0-2][gh-2][w]  (may point pre-buffer; guarded loads)
    const float* bp  = x2b + ((size_t)(d0 - 2)) * 4096 + (size_t)(gh - 2) * 64 + w;
    const float* x1p = x1b + (size_t)d0 * 4096 + (size_t)gh * 64 + w;

    const bool wlo = (w > 0), whi = (w < 62);
    bool pd[6];
    #pragma unroll
    for (int p = 0; p < 6; ++p) pd[p] = ((unsigned)(d0 - 2 + p) < 32u);

    const bool interior = (h0 >= 8) && (h0 <= 48) && (d0 >= 2) && (d0 <= 28);
    if (interior)
        worker<false>(acc, bp, x1p, wlo, whi, true, true, true, true, pd);
    else
        worker<true>(acc, bp, x1p, wlo, whi,
                     gh >= 2, gh >= 1, gh <= 62, gh <= 61, pd);

    // ---- epilogue: scale by 1/125 and store ----
    const uint32_t invb = __float_as_uint(1.0f / 125.0f);
    const ull invv = pk2(invb, invb);
    float* ob = out + (size_t)b * 16384000 + (size_t)d0 * 4096
                    + (size_t)gh * 64 + w;
    #pragma unroll
    for (int a = 0; a < 2; ++a)
        #pragma unroll
        for (int u = 0; u < 5; ++u)
            #pragma unroll
            for (int v = 0; v < 9; ++v) {
                int ch = (5 * (v - 4) + (u - 2)) % 125;
                if (ch < 0) ch += 125;
                ull r = mul2(acc[a][u][v], invv);
                *reinterpret_cast<ull*>(ob + (size_t)ch * 131072 + a * 4096) = r;
            }
}

extern "C" void kernel_launch(void* const* d_in, const int* in_sizes, int n_in,
                              void* d_out, int out_size) {
    const float* x1 = (const float*)d_in[0];
    const float* x2 = (const float*)d_in[1];
    float* out = (float*)d_out;
    cv3d_kernel<<<dim3(8, 16, 2), 256>>>(x1, x2, out);
}

// round 6
// speedup vs baseline: 2.2506x; 2.2506x over previous
#include <cuda_runtime.h>
#include <cstdint>

// CostVolumeLayer3D, B=2 C=64 D=32 H=64 W=64, R=2.
// out[b, ch(s,dsh), d, h, w] = (1/125) * sum_c x1[b,c,d,h,w] * x2[b,c,d-dsh,h-i_s,w-j_s]
//   s in [-4,4], dsh in [-2,2], (i_s,j_s) = (min(2,s+2), max(-2,s-2)),
//   ch = (5s+dsh) mod 125. Channels 23..102 are identically zero.
// Shift-split: group A CTAs compute s=0..4 (row arm), group B CTAs s=-4..-1
// (col arm). Halves acc registers per thread -> 3 CTAs/SM (12 warps) and
// short LDS chains, while keeping full d-pair x2 reuse.

typedef unsigned long long ull;
#define LD64(p) (*reinterpret_cast<const ull*>(p))

static __device__ __forceinline__ void cp16(uint32_t dst, const float* src, int vsz) {
    asm volatile("cp.async.cg.shared.global [%0], [%1], 16, %2;"
                 :: "r"(dst), "l"(src), "r"(vsz));
}
static __device__ __forceinline__ ull pk2(uint32_t lo, uint32_t hi) {
    ull r; asm("mov.b64 %0, {%1,%2};" : "=l"(r) : "r"(lo), "r"(hi)); return r;
}
static __device__ __forceinline__ void unpk(uint32_t& lo, uint32_t& hi, ull v) {
    asm("mov.b64 {%0,%1}, %2;" : "=r"(lo), "=r"(hi) : "l"(v));
}
static __device__ __forceinline__ void fma2(ull& acc, ull a, ull b) {
    asm("fma.rn.f32x2 %0, %1, %2, %0;" : "+l"(acc) : "l"(a), "l"(b));
}
static __device__ __forceinline__ ull mul2(ull a, ull b) {
    ull r; asm("mul.rn.f32x2 %0, %1, %2;" : "=l"(r) : "l"(a), "l"(b)); return r;
}

// Per-buffer smem (floats): x2 only, 6 planes * (8 rows * 72 cols) = 3456
// (13824 B); smem col = global_w + 4 (W halo cols 2,3,68,69). 3 buffers.
extern __shared__ float sm[];

// GRP 0: s = 0..4 (NS=5).  GRP 1: s = -4..-1 (NS=4).
template<int GRP>
static __device__ __forceinline__ void run(
    int tid, int hl, int w, int h0, int d0,
    const float* __restrict__ x1b, const float* __restrict__ x2b,
    float* __restrict__ outb)
{
    constexpr int NS = GRP ? 4 : 5;
    const uint32_t smb = (uint32_t)__cvta_generic_to_shared(sm);

    // ---- compact cp.async geometry: chunk q = tid + 128k => plane k,
    //      row = tid>>4 (8 rows), cw = tid&15 (16 x 16B chunks) ----
    const int crow = tid >> 4, ccw = tid & 15;
    const int ghl  = h0 - 2 + crow;
    const bool ghok = ((unsigned)ghl < 64u);
    const float* srow = x2b + (size_t)(ghok ? ghl : 0) * 64 + ccw * 4;
    const uint32_t cdst0 = smb + (uint32_t)(crow * 72 + 4 + ccw * 4) * 4u;
    int gdc[6], vz[6];
    #pragma unroll
    for (int k = 0; k < 6; ++k) {
        int gd = d0 - 2 + k;
        vz[k]  = (ghok && (unsigned)gd < 32u) ? 16 : 0;
        gdc[k] = gd < 0 ? 0 : (gd > 31 ? 31 : gd);
    }

    // ---- prologue: prefetch channels 0 (buf0) and 1 (buf1) ----
    #pragma unroll
    for (int pr = 0; pr < 2; ++pr) {
        #pragma unroll
        for (int k = 0; k < 6; ++k)
            cp16(cdst0 + (uint32_t)k * 2304u + (uint32_t)pr * 13824u,
                 srow + (size_t)gdc[k] * 4096 + (size_t)pr * 131072, vz[k]);
        asm volatile("cp.async.commit_group;");
    }

    // ---- zero W-halo columns of all 3 buffers (image edge => always 0) ----
    for (int q = tid; q < 144; q += 128) {
        int buf = q / 48, r = q % 48, pl = r >> 3, row = r & 7;
        float* hp = sm + buf * 3456 + pl * 576 + row * 72;
        hp[2] = 0.f; hp[3] = 0.f; hp[68] = 0.f; hp[69] = 0.f;
    }

    // ---- zero 40 of the 80 never-written channels (A:23..62, B:63..102) ----
    {
        float* zb = outb + (size_t)(23 + GRP * 40) * 131072
                         + (size_t)d0 * 4096 + (size_t)h0 * 64;
        int dd = (tid >> 6) & 1, row = (tid >> 4) & 3, cw = tid & 15;
        float* base = zb + dd * 4096 + row * 64 + cw * 4;
        const float4 z = make_float4(0.f, 0.f, 0.f, 0.f);
        #pragma unroll 4
        for (int ch = 0; ch < 40; ++ch)
            *reinterpret_cast<float4*>(base + (size_t)ch * 131072) = z;
    }

    // ---- x1 register stream, prefetched one channel ahead ----
    const float* x1p = x1b + (size_t)d0 * 4096 + (size_t)(h0 + hl) * 64 + w;
    ull A0 = LD64(x1p), A1 = LD64(x1p + 4096);

    // ---- accumulators [d][dsh+2][sv] ----
    ull acc[2][5][NS];
    #pragma unroll
    for (int a = 0; a < 2; ++a)
        #pragma unroll
        for (int u = 0; u < 5; ++u)
            #pragma unroll
            for (int v = 0; v < NS; ++v) acc[a][u][v] = 0ull;

    int cb = 0, pb = 2;
    #pragma unroll 1
    for (int c = 0; c < 64; ++c) {
        if (c < 63) asm volatile("cp.async.wait_group 1;");
        else        asm volatile("cp.async.wait_group 0;");
        __syncthreads();

        ull N0 = 0, N1 = 0;
        if (c < 63) {
            const float* nx = x1p + (size_t)(c + 1) * 131072;
            N0 = LD64(nx); N1 = LD64(nx + 4096);
        }
        if (c < 62) {
            const uint32_t pbo = (uint32_t)pb * 13824u;
            const float* sc = srow + (size_t)(c + 2) * 131072;
            #pragma unroll
            for (int k = 0; k < 6; ++k)
                cp16(cdst0 + (uint32_t)k * 2304u + pbo,
                     sc + (size_t)gdc[k] * 4096, vz[k]);
            asm volatile("cp.async.commit_group;");
        }

        const float* xw = sm + cb * 3456 + hl * 72 + (w + 4); // row gh-2, col w
        #pragma unroll
        for (int p = 0; p < 6; ++p) {                 // x2 plane gd = d0-2+p
            const float* pp = xw + p * 576;
            ull bb[NS];
            if (GRP == 0) {                           // row arm: s = 0..4
                ull f0 = LD64(pp - 2);                // (gh-2, w-2..w-1)
                ull f2 = LD64(pp);                    // (gh-2, w..w+1)
                ull f4 = LD64(pp + 2);                // (gh-2, w+2..w+3)
                uint32_t f0lo, f0hi, f2lo, f2hi, f4lo, f4hi;
                unpk(f0lo, f0hi, f0); unpk(f2lo, f2hi, f2); unpk(f4lo, f4hi, f4);
                bb[0] = f4;                 // s=0
                bb[1] = pk2(f2hi, f4lo);    // s=1
                bb[2] = f2;                 // s=2
                bb[3] = pk2(f0hi, f2lo);    // s=3
                bb[4] = f0;                 // s=4
            } else {                                  // col arm: s = -4..-1
                bb[0] = LD64(pp + 290);     // s=-4: (gh+2, w+2)
                bb[1] = LD64(pp + 218);     // s=-3: (gh+1, w+2)
                bb[2] = LD64(pp + 146);     // s=-2: (gh,   w+2)
                bb[3] = LD64(pp + 74);      // s=-1: (gh-1, w+2)
            }
            if (p <= 4) {                   // voxel d0:   u = 4-p
                #pragma unroll
                for (int v = 0; v < NS; ++v) fma2(acc[0][4 - p][v], A0, bb[v]);
            }
            if (p >= 1) {                   // voxel d0+1: u = 5-p
                #pragma unroll
                for (int v = 0; v < NS; ++v) fma2(acc[1][5 - p][v], A1, bb[v]);
            }
        }

        A0 = N0; A1 = N1;
        cb = (cb == 2) ? 0 : cb + 1;
        pb = (pb == 2) ? 0 : pb + 1;
    }

    // ---- epilogue: scale by 1/125 and store ----
    const uint32_t invb = __float_as_uint(1.0f / 125.0f);
    const ull invv = pk2(invb, invb);
    float* ob = outb + (size_t)d0 * 4096 + (size_t)(h0 + hl) * 64 + w;
    #pragma unroll
    for (int a = 0; a < 2; ++a)
        #pragma unroll
        for (int u = 0; u < 5; ++u)
            #pragma unroll
            for (int v = 0; v < NS; ++v) {
                int s  = GRP ? (v - 4) : v;
                int ch = 5 * s + (u - 2);
                if (ch < 0) ch += 125;
                ull r = mul2(acc[a][u][v], invv);
                *reinterpret_cast<ull*>(ob + (size_t)ch * 131072 + a * 4096) = r;
            }
}

__global__ void __launch_bounds__(128, 3)
cv3d_kernel(const float* __restrict__ x1, const float* __restrict__ x2,
            float* __restrict__ out)
{
    const int tid = threadIdx.x;
    const int hl  = tid >> 5;           // 0..3: h row (warp = one row)
    const int w   = (tid & 31) * 2;     // even w; thread owns (w, w+1)
    const int h0  = blockIdx.x * 4;
    const int d0  = blockIdx.y * 2;
    const int b   = blockIdx.z >> 1;
    const int grp = blockIdx.z & 1;

    const float* x1b = x1 + (size_t)b * 8388608;
    const float* x2b = x2 + (size_t)b * 8388608;
    float* outb = out + (size_t)b * 16384000;

    if (grp == 0) run<0>(tid, hl, w, h0, d0, x1b, x2b, outb);
    else          run<1>(tid, hl, w, h0, d0, x1b, x2b, outb);
}

extern "C" void kernel_launch(void* const* d_in, const int* in_sizes, int n_in,
                              void* d_out, int out_size) {
    const float* x1 = (const float*)d_in[0];
    const float* x2 = (const float*)d_in[1];
    float* out = (float*)d_out;
    cudaFuncSetAttribute(cv3d_kernel,
                         cudaFuncAttributeMaxDynamicSharedMemorySize, 41472);
    cv3d_kernel<<<dim3(16, 16, 4), 128, 41472>>>(x1, x2, out);
}